// round 1
// baseline (speedup 1.0000x reference)
#include <cuda_runtime.h>

// ---------------- problem constants ----------------
#define NB    32      // batch
#define NH    32      // q heads
#define NKV   8       // kv heads
#define HD    128     // head dim
#define DIM   4096
#define NQKV  6144    // (32 + 16) * 128
#define KVLEN 4096
#define SPLITS 8      // L-splits in attention
#define CHUNK  256    // positions per attention block
#define KSP    8      // k-splits for GEMMs
#define KR    (DIM / KSP)   // 512

typedef unsigned long long ull;

// ---------------- f32x2 helpers (FFMA2 path, PTX-only per sm_103a) ----------------
__device__ __forceinline__ ull pack2(float x, float y) {
    ull r; asm("mov.b64 %0,{%1,%2};" : "=l"(r) : "f"(x), "f"(y)); return r;
}
__device__ __forceinline__ float2 unpk(ull v) {
    float lo, hi; asm("mov.b64 {%0,%1},%2;" : "=f"(lo), "=f"(hi) : "l"(v));
    return make_float2(lo, hi);
}
__device__ __forceinline__ void fma2(ull& d, ull a, ull b) {
    asm("fma.rn.f32x2 %0,%1,%2,%0;" : "+l"(d) : "l"(a), "l"(b));
}
__device__ __forceinline__ float ex2(float x) {
    float r; asm("ex2.approx.ftz.f32 %0,%1;" : "=f"(r) : "f"(x)); return r;
}

// ---------------- scratch (device globals; no allocations allowed) ----------------
__device__ float g_pqkv[KSP * NB * NQKV];          // qkv GEMM partials
__device__ float g_q   [NB * NH * HD];             // rotated+scaled q
__device__ float g_kn  [NB * NKV * HD];            // rotated new k
__device__ float g_vn  [NB * NKV * HD];            // new v
__device__ float g_pm  [NB * NKV * 4 * SPLITS];    // per-split max
__device__ float g_pl  [NB * NKV * 4 * SPLITS];    // per-split sum
__device__ float g_pacc[NB * NKV * 4 * SPLITS * HD];
__device__ float g_attn[NB * DIM];                 // combined attention out
__device__ float g_po  [KSP * NB * DIM];           // wo GEMM partials

// ---------------- GEMM: out[b][j] = sum_k X[b][k] * W[k][j]  (split-K partials) ----
// grid: (NOUT/128, KSP), block 256.  thread: tx owns 4 consecutive j, ty owns 4 batches.
template<int NOUT>
__global__ void __launch_bounds__(256) gemm_kernel(
    const float* __restrict__ X, const float* __restrict__ W, float* __restrict__ part)
{
    __shared__ float xs[32 * 70];    // xs[kk][2b],[2b+1] duplicated pairs, stride 70
    const int tid = threadIdx.x;
    const int tx = tid & 31, ty = tid >> 5;
    const int j0 = blockIdx.x * 128 + tx * 4;
    const int k0 = blockIdx.y * KR;

    ull acc[8];
    #pragma unroll
    for (int i = 0; i < 8; i++) acc[i] = 0ULL;

    for (int kt = 0; kt < KR; kt += 32) {
        // cooperative tile load: 32 batches x 32 k, duplicated for (x,x) pairs
        #pragma unroll
        for (int r = 0; r < 4; r++) {
            int e = tid + r * 256;
            int bb = e >> 5, kk = e & 31;
            float v = X[bb * DIM + k0 + kt + kk];
            xs[kk * 70 + 2 * bb]     = v;
            xs[kk * 70 + 2 * bb + 1] = v;
        }
        __syncthreads();
        const float* wp = W + (size_t)(k0 + kt) * NOUT + j0;
        #pragma unroll 8
        for (int kk = 0; kk < 32; kk++) {
            ulonglong2 w2 = *(const ulonglong2*)wp;   // (w_j0,w_j0+1),(w_j0+2,w_j0+3)
            wp += NOUT;
            const ull* xr = (const ull*)(xs + kk * 70 + 8 * ty);
            #pragma unroll
            for (int bi = 0; bi < 4; bi++) {
                ull xb = xr[bi];                       // (x_b, x_b)
                fma2(acc[bi * 2 + 0], w2.x, xb);
                fma2(acc[bi * 2 + 1], w2.y, xb);
            }
        }
        __syncthreads();
    }
    #pragma unroll
    for (int bi = 0; bi < 4; bi++) {
        float2 a = unpk(acc[bi * 2]), c = unpk(acc[bi * 2 + 1]);
        float4 o = make_float4(a.x, a.y, c.x, c.y);
        int bb = ty * 4 + bi;
        *(float4*)&part[((size_t)blockIdx.y * NB + bb) * NOUT + j0] = o;
    }
}

// ---------------- reduce qkv partials + RoPE + split ----------------
// grid (NB, 6): y=0..3 -> q head-groups of 8, y=4 -> k heads, y=5 -> v copy
__global__ void __launch_bounds__(256) rope_kernel(const float* __restrict__ rot)
{
    const int b = blockIdx.x, y = blockIdx.y;
    const int tid = threadIdx.x;
    __shared__ float xsm[HD * 10];   // xsm[d][r], 8 rows, stride 10

    if (y < 5) {
        const int jb = (y < 4) ? y * 8 * HD : NH * HD;
        for (int e = tid; e < 8 * HD; e += 256) {
            int r = e >> 7, d = e & 127;
            float s = 0.f;
            #pragma unroll
            for (int p = 0; p < KSP; p++)
                s += g_pqkv[(size_t)p * NB * NQKV + b * NQKV + jb + r * HD + d];
            xsm[d * 10 + r] = s;
        }
        __syncthreads();
        const int e = tid & 127, ty = tid >> 7;     // rows 4*ty .. 4*ty+3
        ull a0 = 0, a1 = 0;
        const float* rp = rot + e;
        for (int d = 0; d < HD; d++) {
            float rv = rp[d * HD];
            ull rr = pack2(rv, rv);
            const ull* xr = (const ull*)(xsm + d * 10 + 4 * ty);
            fma2(a0, xr[0], rr);
            fma2(a1, xr[1], rr);
        }
        float2 f0 = unpk(a0), f1 = unpk(a1);
        float out4[4] = { f0.x, f0.y, f1.x, f1.y };
        if (y < 4) {
            const float sc = 0.08838834764831845f * 1.4426950408889634f; // 128^-.5 * log2(e)
            #pragma unroll
            for (int i = 0; i < 4; i++)
                g_q[(b * NH + y * 8 + ty * 4 + i) * HD + e] = out4[i] * sc;
        } else {
            #pragma unroll
            for (int i = 0; i < 4; i++)
                g_kn[(b * NKV + ty * 4 + i) * HD + e] = out4[i];
        }
    } else {
        for (int e = tid; e < NKV * HD; e += 256) {
            float s = 0.f;
            #pragma unroll
            for (int p = 0; p < KSP; p++)
                s += g_pqkv[(size_t)p * NB * NQKV + b * NQKV + (NH + NKV) * HD + e];
            g_vn[b * NKV * HD + e] = s;
        }
    }
}

// ---------------- flash-decode attention (split-L) ----------------
// grid (SPLITS, NKV, NB), block 256 (8 warps). Warp handles one position per step.
// Lane layout phase1: g = lane&3 (q head within group), dblk = lane>>2 (16-d slab)
//   -> dot reduce needs only xor 4/8/16 (3 SHFLs).
__global__ void __launch_bounds__(256) attn_kernel(
    const float* __restrict__ cache_k, const float* __restrict__ cache_v,
    const int* __restrict__ curp)
{
    const int sp = blockIdx.x, kv = blockIdx.y, b = blockIdx.z;
    const int cur = curp[0];
    const int tid = threadIdx.x;
    const int w = tid >> 5, L = tid & 31;
    const int g = L & 3, dblk = L >> 2;

    __shared__ float sbuf[4096];     // phase1-2: p[s][g] (first 1024); end: warp partials
    __shared__ float wredm[32], wredl[32], bm[4];

    // q in registers: lane needs q[head kv*4+g][dblk*16 .. +15]
    ull q2[8];
    {
        const float* qp = &g_q[(b * NH + kv * 4 + g) * HD + dblk * 16];
        #pragma unroll
        for (int i = 0; i < 4; i++) {
            ulonglong2 t = *(const ulonglong2*)(qp + i * 4);
            q2[i * 2] = t.x; q2[i * 2 + 1] = t.y;
        }
    }

    const int s0 = sp * CHUNK;
    const float* kbase = cache_k + (size_t)(b * NKV + kv) * KVLEN * HD;
    float mloc = -1e30f;

    // ---- phase 1: scores (in log2 domain, q pre-scaled) ----
    for (int i = 0; i < CHUNK / 8; i++) {
        int s = s0 + i * 8 + w;
        const float* kp = (s == cur) ? &g_kn[(b * NKV + kv) * HD] : kbase + (size_t)s * HD;
        const ulonglong2* kp2 = (const ulonglong2*)(kp + dblk * 16);
        ull aa = 0, ab = 0;
        #pragma unroll
        for (int ii = 0; ii < 4; ii++) {
            ulonglong2 kk = kp2[ii];
            fma2(aa, kk.x, q2[ii * 2]);
            fma2(ab, kk.y, q2[ii * 2 + 1]);
        }
        float2 fa = unpk(aa), fb = unpk(ab);
        float v = (fa.x + fa.y) + (fb.x + fb.y);
        v += __shfl_xor_sync(0xffffffffu, v, 4);
        v += __shfl_xor_sync(0xffffffffu, v, 8);
        v += __shfl_xor_sync(0xffffffffu, v, 16);
        if (s > cur) v = -1e30f;
        mloc = fmaxf(mloc, v);
        if (L < 4) sbuf[(i * 8 + w) * 4 + L] = v;
    }
    if (L < 4) wredm[w * 4 + L] = mloc;
    __syncthreads();
    if (tid < 4) {
        float m = wredm[tid];
        #pragma unroll
        for (int ww = 1; ww < 8; ww++) m = fmaxf(m, wredm[ww * 4 + tid]);
        bm[tid] = m;
    }
    __syncthreads();

    // ---- phase 2: exp2 + row sums ----
    {
        float m = bm[g];
        float lsum = 0.f;
        int sl0 = tid >> 2;    // 0..63
        #pragma unroll
        for (int t = 0; t < CHUNK / 64; t++) {
            int idx = (sl0 + t * 64) * 4 + g;
            float p = ex2(sbuf[idx] - m);
            sbuf[idx] = p;
            lsum += p;
        }
        lsum += __shfl_xor_sync(0xffffffffu, lsum, 4);
        lsum += __shfl_xor_sync(0xffffffffu, lsum, 8);
        lsum += __shfl_xor_sync(0xffffffffu, lsum, 16);
        if (L < 4) wredl[w * 4 + L] = lsum;
    }
    __syncthreads();
    float myl = 0.f;
    if (tid < 4) {
        #pragma unroll
        for (int ww = 0; ww < 8; ww++) myl += wredl[ww * 4 + tid];
    }

    // ---- phase 3: P @ V  (lane covers d = 4L..4L+3 for all 4 heads) ----
    const float* vbase = cache_v + (size_t)(b * NKV + kv) * KVLEN * HD;
    ull av[8];
    #pragma unroll
    for (int i = 0; i < 8; i++) av[i] = 0ULL;

    for (int i = 0; i < CHUNK / 8; i++) {
        int s = s0 + i * 8 + w;
        const float* vp = (s == cur) ? &g_vn[(b * NKV + kv) * HD] : vbase + (size_t)s * HD;
        ulonglong2 v2 = *(const ulonglong2*)(vp + L * 4);
        float4 p4 = *(const float4*)&sbuf[(i * 8 + w) * 4];
        ull p0 = pack2(p4.x, p4.x), p1 = pack2(p4.y, p4.y);
        ull p2 = pack2(p4.z, p4.z), p3 = pack2(p4.w, p4.w);
        fma2(av[0], v2.x, p0); fma2(av[1], v2.y, p0);
        fma2(av[2], v2.x, p1); fma2(av[3], v2.y, p1);
        fma2(av[4], v2.x, p2); fma2(av[5], v2.y, p2);
        fma2(av[6], v2.x, p3); fma2(av[7], v2.y, p3);
    }
    __syncthreads();   // all p reads done; reuse sbuf for cross-warp reduce

    #pragma unroll
    for (int gg = 0; gg < 4; gg++) {
        *(ull*)&sbuf[w * 512 + gg * 128 + L * 4]     = av[gg * 2];
        *(ull*)&sbuf[w * 512 + gg * 128 + L * 4 + 2] = av[gg * 2 + 1];
    }
    __syncthreads();

    #pragma unroll
    for (int r = 0; r < 2; r++) {
        int o = tid + r * 256;           // o = gg*128 + d
        float s = 0.f;
        #pragma unroll
        for (int ww = 0; ww < 8; ww++) s += sbuf[ww * 512 + o];
        int gg = o >> 7, d = o & 127;
        int base = ((b * NKV + kv) * 4 + gg) * SPLITS + sp;
        g_pacc[(size_t)base * HD + d] = s;
    }
    if (tid < 4) {
        int base = ((b * NKV + kv) * 4 + tid) * SPLITS + sp;
        g_pm[base] = bm[tid];
        g_pl[base] = myl;
    }
}

// ---------------- combine L-splits ----------------
// grid (NH, NB), block 128 (thread = d)
__global__ void __launch_bounds__(128) combine_kernel()
{
    const int h = blockIdx.x, b = blockIdx.y;
    const int kv = h >> 2, gg = h & 3;
    const int base = ((b * NKV + kv) * 4 + gg) * SPLITS;
    const int d = threadIdx.x;
    float m = -1e30f;
    #pragma unroll
    for (int sp = 0; sp < SPLITS; sp++) m = fmaxf(m, g_pm[base + sp]);
    float num = 0.f, den = 0.f;
    #pragma unroll
    for (int sp = 0; sp < SPLITS; sp++) {
        float wgt = ex2(g_pm[base + sp] - m);
        den += wgt * g_pl[base + sp];
        num += wgt * g_pacc[(size_t)(base + sp) * HD + d];
    }
    g_attn[b * DIM + h * HD + d] = num / den;
}

// ---------------- final reduce of wo partials ----------------
__global__ void __launch_bounds__(256) wored_kernel(float* __restrict__ out)
{
    int e = blockIdx.x * 256 + threadIdx.x;
    float s = 0.f;
    #pragma unroll
    for (int p = 0; p < KSP; p++) s += g_po[(size_t)p * NB * DIM + e];
    out[e] = s;
}

// ---------------- launch ----------------
extern "C" void kernel_launch(void* const* d_in, const int* in_sizes, int n_in,
                              void* d_out, int out_size)
{
    const float* attn_norm = (const float*)d_in[0];
    const float* wqkv      = (const float*)d_in[1];
    const float* wo        = (const float*)d_in[2];
    const float* rot       = (const float*)d_in[3];
    const float* cache_k   = (const float*)d_in[4];
    const float* cache_v   = (const float*)d_in[5];
    const int*   curp      = (const int*)d_in[6];

    float *pq = 0, *po = 0, *pat = 0;
    cudaGetSymbolAddress((void**)&pq,  g_pqkv);
    cudaGetSymbolAddress((void**)&po,  g_po);
    cudaGetSymbolAddress((void**)&pat, g_attn);

    dim3 gA(NQKV / 128, KSP);
    gemm_kernel<NQKV><<<gA, 256>>>(attn_norm, wqkv, pq);

    dim3 gR(NB, 6);
    rope_kernel<<<gR, 256>>>(rot);

    dim3 gAt(SPLITS, NKV, NB);
    attn_kernel<<<gAt, 256>>>(cache_k, cache_v, curp);

    dim3 gC(NH, NB);
    combine_kernel<<<gC, 128>>>();

    dim3 gO(DIM / 128, KSP);
    gemm_kernel<DIM><<<gO, 256>>>(pat, wo, po);

    wored_kernel<<<NB * DIM / 256, 256>>>((float*)d_out);
}

// round 3
// speedup vs baseline: 1.1348x; 1.1348x over previous
#include <cuda_runtime.h>

// ---------------- problem constants ----------------
#define NB    32      // batch
#define NH    32      // q heads
#define NKV   8       // kv heads
#define HD    128     // head dim
#define DIM   4096
#define NQKV  6144    // (32 + 16) * 128
#define KVLEN 4096
#define SPLITS 8      // L-splits in attention
#define CHUNK  256    // positions per attention block
#define TILE   32     // positions per smem stage
#define KSP    8      // k-splits for GEMMs
#define KR    (DIM / KSP)   // 512

typedef unsigned long long ull;

// ---------------- f32x2 helpers (FFMA2 path, PTX-only per sm_103a) ----------------
__device__ __forceinline__ ull pack2(float x, float y) {
    ull r; asm("mov.b64 %0,{%1,%2};" : "=l"(r) : "f"(x), "f"(y)); return r;
}
__device__ __forceinline__ float2 unpk(ull v) {
    float lo, hi; asm("mov.b64 {%0,%1},%2;" : "=f"(lo), "=f"(hi) : "l"(v));
    return make_float2(lo, hi);
}
__device__ __forceinline__ void fma2(ull& d, ull a, ull b) {
    asm("fma.rn.f32x2 %0,%1,%2,%0;" : "+l"(d) : "l"(a), "l"(b));
}
__device__ __forceinline__ float ex2(float x) {
    float r; asm("ex2.approx.ftz.f32 %0,%1;" : "=f"(r) : "f"(x)); return r;
}
__device__ __forceinline__ void cpa16(void* s, const void* gp) {
    unsigned sa = (unsigned)__cvta_generic_to_shared(s);
    asm volatile("cp.async.cg.shared.global [%0], [%1], 16;" :: "r"(sa), "l"(gp));
}

// ---------------- scratch (device globals; no allocations allowed) ----------------
__device__ float g_pqkv[KSP * NB * NQKV];          // qkv GEMM partials
__device__ float g_q   [NB * NH * HD];             // rotated+scaled q
__device__ float g_kn  [NB * NKV * HD];            // rotated new k
__device__ float g_vn  [NB * NKV * HD];            // new v
__device__ float g_pm  [NB * NKV * 4 * SPLITS];    // per-split max
__device__ float g_pl  [NB * NKV * 4 * SPLITS];    // per-split sum
__device__ float g_pacc[NB * NKV * 4 * SPLITS * HD];
__device__ float g_attn[NB * DIM];                 // combined attention out
__device__ float g_po  [KSP * NB * DIM];           // wo GEMM partials

// ---------------- GEMM: out[b][j] = sum_k X[b][k] * W[k][j]  (split-K partials) ----
template<int NOUT>
__global__ void __launch_bounds__(256) gemm_kernel(
    const float* __restrict__ X, const float* __restrict__ W, float* __restrict__ part)
{
    __shared__ float xs[32 * 70];    // xs[kk][2b],[2b+1] duplicated pairs, stride 70
    const int tid = threadIdx.x;
    const int tx = tid & 31, ty = tid >> 5;
    const int j0 = blockIdx.x * 128 + tx * 4;
    const int k0 = blockIdx.y * KR;

    ull acc[8];
    #pragma unroll
    for (int i = 0; i < 8; i++) acc[i] = 0ULL;

    for (int kt = 0; kt < KR; kt += 32) {
        #pragma unroll
        for (int r = 0; r < 4; r++) {
            int e = tid + r * 256;
            int bb = e >> 5, kk = e & 31;
            float v = X[bb * DIM + k0 + kt + kk];
            xs[kk * 70 + 2 * bb]     = v;
            xs[kk * 70 + 2 * bb + 1] = v;
        }
        __syncthreads();
        const float* wp = W + (size_t)(k0 + kt) * NOUT + j0;
        #pragma unroll 8
        for (int kk = 0; kk < 32; kk++) {
            ulonglong2 w2 = *(const ulonglong2*)wp;
            wp += NOUT;
            const ull* xr = (const ull*)(xs + kk * 70 + 8 * ty);
            #pragma unroll
            for (int bi = 0; bi < 4; bi++) {
                ull xb = xr[bi];
                fma2(acc[bi * 2 + 0], w2.x, xb);
                fma2(acc[bi * 2 + 1], w2.y, xb);
            }
        }
        __syncthreads();
    }
    #pragma unroll
    for (int bi = 0; bi < 4; bi++) {
        float2 a = unpk(acc[bi * 2]), c = unpk(acc[bi * 2 + 1]);
        float4 o = make_float4(a.x, a.y, c.x, c.y);
        int bb = ty * 4 + bi;
        *(float4*)&part[((size_t)blockIdx.y * NB + bb) * NOUT + j0] = o;
    }
}

// ---------------- reduce qkv partials + RoPE + split ----------------
__global__ void __launch_bounds__(256) rope_kernel(const float* __restrict__ rot)
{
    const int b = blockIdx.x, y = blockIdx.y;
    const int tid = threadIdx.x;
    __shared__ float xsm[HD * 10];

    if (y < 5) {
        const int jb = (y < 4) ? y * 8 * HD : NH * HD;
        for (int e = tid; e < 8 * HD; e += 256) {
            int r = e >> 7, d = e & 127;
            float s = 0.f;
            #pragma unroll
            for (int p = 0; p < KSP; p++)
                s += g_pqkv[(size_t)p * NB * NQKV + b * NQKV + jb + r * HD + d];
            xsm[d * 10 + r] = s;
        }
        __syncthreads();
        const int e = tid & 127, ty = tid >> 7;
        ull a0 = 0, a1 = 0;
        const float* rp = rot + e;
        for (int d = 0; d < HD; d++) {
            float rv = rp[d * HD];
            ull rr = pack2(rv, rv);
            const ull* xr = (const ull*)(xsm + d * 10 + 4 * ty);
            fma2(a0, xr[0], rr);
            fma2(a1, xr[1], rr);
        }
        float2 f0 = unpk(a0), f1 = unpk(a1);
        float out4[4] = { f0.x, f0.y, f1.x, f1.y };
        if (y < 4) {
            const float sc = 0.08838834764831845f * 1.4426950408889634f;
            #pragma unroll
            for (int i = 0; i < 4; i++)
                g_q[(b * NH + y * 8 + ty * 4 + i) * HD + e] = out4[i] * sc;
        } else {
            #pragma unroll
            for (int i = 0; i < 4; i++)
                g_kn[(b * NKV + ty * 4 + i) * HD + e] = out4[i];
        }
    } else {
        for (int e = tid; e < NKV * HD; e += 256) {
            float s = 0.f;
            #pragma unroll
            for (int p = 0; p < KSP; p++)
                s += g_pqkv[(size_t)p * NB * NQKV + b * NQKV + (NH + NKV) * HD + e];
            g_vn[b * NKV * HD + e] = s;
        }
    }
}

// ---------------- flash-decode attention (split-L, cp.async smem pipeline) ----------
// grid (SPLITS, NKV, NB), block 256 (8 warps).
// K and V slabs streamed as contiguous 16 KB tiles (32 pos x 512 B) through a
// double-buffered smem ring. Compute reads smem only.
__global__ void __launch_bounds__(256) attn_kernel(
    const float* __restrict__ cache_k, const float* __restrict__ cache_v,
    const int* __restrict__ curp)
{
    const int sp = blockIdx.x, kv = blockIdx.y, b = blockIdx.z;
    const int cur = curp[0];
    const int tid = threadIdx.x;
    const int w = tid >> 5, L = tid & 31;
    const int g = L & 3, dblk = L >> 2;

    __shared__ float kt[2][TILE * HD];   // 2 x 16 KB staging buffers
    __shared__ float sbuf[CHUNK * 4];    // scores / probs [s][g]
    __shared__ float wredm[32], wredl[32], bm[4];

    // q in registers: lane needs q[head kv*4+g][dblk*16 .. +15]
    ull q2[8];
    {
        const float* qp = &g_q[(b * NH + kv * 4 + g) * HD + dblk * 16];
        #pragma unroll
        for (int i = 0; i < 4; i++) {
            ulonglong2 t = *(const ulonglong2*)(qp + i * 4);
            q2[i * 2] = t.x; q2[i * 2 + 1] = t.y;
        }
    }

    const int s0 = sp * CHUNK;
    const float* kbase = cache_k + ((size_t)(b * NKV + kv) * KVLEN + s0) * HD;
    const float* vbase = cache_v + ((size_t)(b * NKV + kv) * KVLEN + s0) * HD;
    const float* knrow = &g_kn[(b * NKV + kv) * HD];
    const float* vnrow = &g_vn[(b * NKV + kv) * HD];

    float mloc = -1e30f;

    // ---- phase 1: stream K, compute scores (log2 domain; q pre-scaled) ----
    {
        #pragma unroll
        for (int r = 0; r < 4; r++)
            cpa16(&kt[0][tid * 4 + r * 1024], kbase + tid * 4 + r * 1024);
        asm volatile("cp.async.commit_group;" ::: "memory");
    }
    for (int t = 0; t < CHUNK / TILE; t++) {
        const int buf = t & 1;
        if (t < CHUNK / TILE - 1) {
            const float* src = kbase + (t + 1) * TILE * HD;
            #pragma unroll
            for (int r = 0; r < 4; r++)
                cpa16(&kt[buf ^ 1][tid * 4 + r * 1024], src + tid * 4 + r * 1024);
            asm volatile("cp.async.commit_group;" ::: "memory");
            asm volatile("cp.async.wait_group 1;" ::: "memory");
        } else {
            asm volatile("cp.async.wait_group 0;" ::: "memory");
        }
        __syncthreads();
        int cl = cur - s0 - t * TILE;
        if (cl >= 0 && cl < TILE && tid < HD) kt[buf][cl * HD + tid] = knrow[tid];
        __syncthreads();

        #pragma unroll
        for (int j = 0; j < 4; j++) {
            int p = j * 8 + w;
            const ulonglong2* kp2 = (const ulonglong2*)&kt[buf][p * HD + dblk * 16];
            ull aa = 0, ab = 0;
            #pragma unroll
            for (int ii = 0; ii < 4; ii++) {
                ulonglong2 kk = kp2[ii];
                fma2(aa, kk.x, q2[ii * 2]);
                fma2(ab, kk.y, q2[ii * 2 + 1]);
            }
            float2 fa = unpk(aa), fb = unpk(ab);
            float v = (fa.x + fa.y) + (fb.x + fb.y);
            v += __shfl_xor_sync(0xffffffffu, v, 4);
            v += __shfl_xor_sync(0xffffffffu, v, 8);
            v += __shfl_xor_sync(0xffffffffu, v, 16);
            int s = s0 + t * TILE + p;
            if (s > cur) v = -1e30f;
            mloc = fmaxf(mloc, v);
            if (L < 4) sbuf[(t * TILE + p) * 4 + L] = v;
        }
        __syncthreads();
    }

    if (L < 4) wredm[w * 4 + L] = mloc;
    __syncthreads();
    if (tid < 4) {
        float m = wredm[tid];
        #pragma unroll
        for (int ww = 1; ww < 8; ww++) m = fmaxf(m, wredm[ww * 4 + tid]);
        bm[tid] = m;
    }

    // prefetch V tile 0 while softmax runs
    {
        #pragma unroll
        for (int r = 0; r < 4; r++)
            cpa16(&kt[0][tid * 4 + r * 1024], vbase + tid * 4 + r * 1024);
        asm volatile("cp.async.commit_group;" ::: "memory");
    }
    __syncthreads();

    // ---- phase 2: exp2 + row sums ----
    {
        float m = bm[g];
        float lsum = 0.f;
        int sl0 = tid >> 2;
        #pragma unroll
        for (int t = 0; t < CHUNK / 64; t++) {
            int idx = (sl0 + t * 64) * 4 + g;
            float p = ex2(sbuf[idx] - m);
            sbuf[idx] = p;
            lsum += p;
        }
        lsum += __shfl_xor_sync(0xffffffffu, lsum, 4);
        lsum += __shfl_xor_sync(0xffffffffu, lsum, 8);
        lsum += __shfl_xor_sync(0xffffffffu, lsum, 16);
        if (L < 4) wredl[w * 4 + L] = lsum;
    }
    __syncthreads();
    float myl = 0.f;
    if (tid < 4) {
        #pragma unroll
        for (int ww = 0; ww < 8; ww++) myl += wredl[ww * 4 + tid];
    }

    // ---- phase 3: stream V, P @ V  (lane covers d = 4L..4L+3, all 4 heads) ----
    ull av[8];
    #pragma unroll
    for (int i = 0; i < 8; i++) av[i] = 0ULL;

    for (int t = 0; t < CHUNK / TILE; t++) {
        const int buf = t & 1;
        if (t < CHUNK / TILE - 1) {
            const float* src = vbase + (t + 1) * TILE * HD;
            #pragma unroll
            for (int r = 0; r < 4; r++)
                cpa16(&kt[buf ^ 1][tid * 4 + r * 1024], src + tid * 4 + r * 1024);
            asm volatile("cp.async.commit_group;" ::: "memory");
            asm volatile("cp.async.wait_group 1;" ::: "memory");
        } else {
            asm volatile("cp.async.wait_group 0;" ::: "memory");
        }
        __syncthreads();
        int cl = cur - s0 - t * TILE;
        if (cl >= 0 && cl < TILE && tid < HD) kt[buf][cl * HD + tid] = vnrow[tid];
        __syncthreads();

        #pragma unroll
        for (int j = 0; j < 4; j++) {
            int p = j * 8 + w;
            ulonglong2 v2 = *(const ulonglong2*)&kt[buf][p * HD + L * 4];
            float4 p4 = *(const float4*)&sbuf[(t * TILE + p) * 4];
            ull p0 = pack2(p4.x, p4.x), p1 = pack2(p4.y, p4.y);
            ull p2 = pack2(p4.z, p4.z), p3 = pack2(p4.w, p4.w);
            fma2(av[0], v2.x, p0); fma2(av[1], v2.y, p0);
            fma2(av[2], v2.x, p1); fma2(av[3], v2.y, p1);
            fma2(av[4], v2.x, p2); fma2(av[5], v2.y, p2);
            fma2(av[6], v2.x, p3); fma2(av[7], v2.y, p3);
        }
        __syncthreads();
    }

    // cross-warp reduce of av through smem (reuse staging buffers)
    float* scr = &kt[0][0];   // 8192 floats available, need 4096
    #pragma unroll
    for (int gg = 0; gg < 4; gg++) {
        *(ull*)&scr[w * 512 + gg * 128 + L * 4]     = av[gg * 2];
        *(ull*)&scr[w * 512 + gg * 128 + L * 4 + 2] = av[gg * 2 + 1];
    }
    __syncthreads();

    #pragma unroll
    for (int r = 0; r < 2; r++) {
        int o = tid + r * 256;           // o = gg*128 + d
        float s = 0.f;
        #pragma unroll
        for (int ww = 0; ww < 8; ww++) s += scr[ww * 512 + o];
        int gg = o >> 7, d = o & 127;
        int base = ((b * NKV + kv) * 4 + gg) * SPLITS + sp;
        g_pacc[(size_t)base * HD + d] = s;
    }
    if (tid < 4) {
        int base = ((b * NKV + kv) * 4 + tid) * SPLITS + sp;
        g_pm[base] = bm[tid];
        g_pl[base] = myl;
    }
}

// ---------------- combine L-splits ----------------
__global__ void __launch_bounds__(128) combine_kernel()
{
    const int h = blockIdx.x, b = blockIdx.y;
    const int kv = h >> 2, gg = h & 3;
    const int base = ((b * NKV + kv) * 4 + gg) * SPLITS;
    const int d = threadIdx.x;
    float m = -1e30f;
    #pragma unroll
    for (int sp = 0; sp < SPLITS; sp++) m = fmaxf(m, g_pm[base + sp]);
    float num = 0.f, den = 0.f;
    #pragma unroll
    for (int sp = 0; sp < SPLITS; sp++) {
        float wgt = ex2(g_pm[base + sp] - m);
        den += wgt * g_pl[base + sp];
        num += wgt * g_pacc[(size_t)(base + sp) * HD + d];
    }
    g_attn[b * DIM + h * HD + d] = num / den;
}

// ---------------- final reduce of wo partials ----------------
__global__ void __launch_bounds__(256) wored_kernel(float* __restrict__ out)
{
    int e = blockIdx.x * 256 + threadIdx.x;
    float s = 0.f;
    #pragma unroll
    for (int p = 0; p < KSP; p++) s += g_po[(size_t)p * NB * DIM + e];
    out[e] = s;
}

// ---------------- launch ----------------
extern "C" void kernel_launch(void* const* d_in, const int* in_sizes, int n_in,
                              void* d_out, int out_size)
{
    const float* attn_norm = (const float*)d_in[0];
    const float* wqkv      = (const float*)d_in[1];
    const float* wo        = (const float*)d_in[2];
    const float* rot       = (const float*)d_in[3];
    const float* cache_k   = (const float*)d_in[4];
    const float* cache_v   = (const float*)d_in[5];
    const int*   curp      = (const int*)d_in[6];

    float *pq = 0, *po = 0, *pat = 0;
    cudaGetSymbolAddress((void**)&pq,  g_pqkv);
    cudaGetSymbolAddress((void**)&po,  g_po);
    cudaGetSymbolAddress((void**)&pat, g_attn);

    dim3 gA(NQKV / 128, KSP);
    gemm_kernel<NQKV><<<gA, 256>>>(attn_norm, wqkv, pq);

    dim3 gR(NB, 6);
    rope_kernel<<<gR, 256>>>(rot);

    dim3 gAt(SPLITS, NKV, NB);
    attn_kernel<<<gAt, 256>>>(cache_k, cache_v, curp);

    dim3 gC(NH, NB);
    combine_kernel<<<gC, 128>>>();

    dim3 gO(DIM / 128, KSP);
    gemm_kernel<DIM><<<gO, 256>>>(pat, wo, po);

    wored_kernel<<<NB * DIM / 256, 256>>>((float*)d_out);
}